// round 11
// baseline (speedup 1.0000x reference)
#include <cuda_runtime.h>
#include <cuda_fp16.h>
#include <math.h>

// Problem constants (fixed shapes: B=2,S=2048,H=2048,E=8,A=64,NS=16384)
#define T_TOK   4096
#define H_DIM   2048
#define E_NUM   8
#define A_NUM   64
#define NS_NUM  16384
#define H_SHIFT 11
#define H_MASK  2047
#define PADMAX  4608
#define MAXBLK  1152

// GEMM: C[T,H] = fp16(x) @ fp16(W)^T, K = 2048, fp32 accumulate
#define KC      2048
#define BM      128
#define BN      256
#define BK      64
#define NCH     (KC / BK)            // 32
#define LDSB    144                  // smem row stride bytes (64 fp16 + 16 pad)
#define ABYTES  (BM * LDSB)          // 18432
#define STAGEB  ((BM + BN) * LDSB)   // 55296
#define NSTG    4
#define SMEM_MMA (NSTG * STAGEB)     // 221184

// ---------------- device scratch (no allocations allowed) ----------------
__device__ __half         g_xh[(size_t)T_TOK * KC];     // 16MB fp16(x)
__device__ __half         g_wh[(size_t)H_DIM * KC];     // 8MB  fp16(W)
__device__ float          g_weighted[E_NUM * NS_NUM];
__device__ float          g_wsrt[E_NUM * NS_NUM];       // weighted, CSR entry order
__device__ int            g_msrt[NS_NUM];               // sorted mask (row<<11|col)
__device__ int            g_counts[H_DIM];
__device__ int            g_rowptr[H_DIM + 1];
__device__ int            g_offsets[H_DIM];
__device__ int            g_e0[T_TOK];
__device__ int            g_e1[T_TOK];
__device__ float          g_rw0[T_TOK];
__device__ float          g_rw1[T_TOK];
// pair grouping (4 tokens per block)
__device__ int            g_paircnt[64];
__device__ int            g_pairoff[64];
__device__ int            g_tokord[PADMAX];
__device__ int            g_blkpair[MAXBLK];
__device__ int            g_total_blocks;

// ---------------- static stream/event resources (created pre-checkpoint) ----------------
struct GraphForkResources {
    cudaStream_t side;
    cudaEvent_t  fork, gemm_done, join;
    GraphForkResources() {
        cudaStreamCreateWithFlags(&side, cudaStreamNonBlocking);
        cudaEventCreateWithFlags(&fork, cudaEventDisableTiming);
        cudaEventCreateWithFlags(&gemm_done, cudaEventDisableTiming);
        cudaEventCreateWithFlags(&join, cudaEventDisableTiming);
    }
};
static GraphForkResources g_fork_res;

// ---------------- ptx helpers (compute_80-level, safe on compute_103) ----------------
__device__ __forceinline__ unsigned smem_u32(const void* p) {
    unsigned r;
    asm("{ .reg .u64 t; cvta.to.shared.u64 t, %1; cvt.u32.u64 %0, t; }" : "=r"(r) : "l"(p));
    return r;
}
__device__ __forceinline__ void cp16(unsigned dst, const void* src) {
    asm volatile("cp.async.cg.shared.global [%0], [%1], 16;\n" :: "r"(dst), "l"(src));
}
__device__ __forceinline__ void cp_commit() { asm volatile("cp.async.commit_group;\n" ::: "memory"); }
__device__ __forceinline__ void cp_wait2()  { asm volatile("cp.async.wait_group 2;\n" ::: "memory"); }
__device__ __forceinline__ void ldsm4(unsigned* r, unsigned addr) {
    asm volatile("ldmatrix.sync.aligned.m8n8.x4.shared.b16 {%0,%1,%2,%3}, [%4];"
                 : "=r"(r[0]), "=r"(r[1]), "=r"(r[2]), "=r"(r[3]) : "r"(addr));
}
__device__ __forceinline__ void mma16816(float* d, const unsigned* a, unsigned b0, unsigned b1) {
    asm volatile(
        "mma.sync.aligned.m16n8k16.row.col.f32.f16.f16.f32 "
        "{%0,%1,%2,%3}, {%4,%5,%6,%7}, {%8,%9}, {%0,%1,%2,%3};"
        : "+f"(d[0]), "+f"(d[1]), "+f"(d[2]), "+f"(d[3])
        : "r"(a[0]), "r"(a[1]), "r"(a[2]), "r"(a[3]), "r"(b0), "r"(b1));
}

// ---------------- fp16 conversion (x and W share row length 2048) ----------------
__global__ __launch_bounds__(256) void convert_fp16_kernel(
    const float* __restrict__ src, __half* __restrict__ dst)
{
    int idx2 = blockIdx.x * 256 + threadIdx.x;          // float2 index
    float2 v = *(const float2*)(src + (size_t)idx2 * 2);
    __half2 h; h.x = __float2half_rn(v.x); h.y = __float2half_rn(v.y);
    *(__half2*)(dst + (size_t)idx2 * 2) = h;
}

// ---------------- HMMA GEMM: out = Xh @ Wh^T ----------------
// 512 threads, 16 warps as 2(m) x 8(n); warp tile 64x32; 4-stage cp.async pipeline.
__global__ __launch_bounds__(512, 1) void mma_gemm_kernel(
    const __half* __restrict__ A,
    const __half* __restrict__ B,
    float* __restrict__ out)
{
    extern __shared__ __align__(128) char sm[];
    const unsigned smb = smem_u32(sm);
    const int tid  = threadIdx.x;
    const int wid  = tid >> 5, lane = tid & 31;
    const int wm   = wid & 1;          // 0..1 (m)
    const int wn   = wid >> 1;         // 0..7 (n)
    const int trow0 = blockIdx.y * BM;
    const int ncol0 = blockIdx.x * BN;

    const int slot = tid & 7;
    const int rr0  = tid >> 3;         // 0..63
    const __half* aP = A + (size_t)(trow0 + rr0) * KC + slot * 8;
    const __half* bP = B + (size_t)(ncol0 + rr0) * KC + slot * 8;
    const unsigned dBase = rr0 * LDSB + slot * 16;

    const unsigned lrow = lane & 15, lhalf = lane >> 4;
    const unsigned aBase = smb + (wm * 64 + lrow) * LDSB + lhalf * 16;
    const unsigned bBase = smb + ABYTES + (wn * 32 + lrow) * LDSB + lhalf * 16;

    float acc[4][4][4];
#pragma unroll
    for (int i = 0; i < 4; i++)
#pragma unroll
        for (int j = 0; j < 4; j++)
#pragma unroll
            for (int r = 0; r < 4; r++) acc[i][j][r] = 0.f;

#pragma unroll
    for (int c = 0; c < 3; c++) {
        unsigned d = smb + c * STAGEB + dBase;
        const __half* ap = aP + c * BK;
        const __half* bp = bP + c * BK;
#pragma unroll
        for (int i = 0; i < 2; i++) { cp16(d, ap); ap += 64 * KC; d += 64 * LDSB; }
#pragma unroll
        for (int i = 0; i < 4; i++) { cp16(d, bp); bp += 64 * KC; d += 64 * LDSB; }
        cp_commit();
    }

    for (int c = 0; c < NCH; c++) {
        cp_wait2();
        __syncthreads();

        int m = c + 3;
        if (m < NCH) {
            unsigned d = smb + (m & 3) * STAGEB + dBase;
            const __half* ap = aP + m * BK;
            const __half* bp = bP + m * BK;
#pragma unroll
            for (int i = 0; i < 2; i++) { cp16(d, ap); ap += 64 * KC; d += 64 * LDSB; }
#pragma unroll
            for (int i = 0; i < 4; i++) { cp16(d, bp); bp += 64 * KC; d += 64 * LDSB; }
        }
        cp_commit();

        unsigned soff = (unsigned)(c & 3) * STAGEB;
#pragma unroll
        for (int ks = 0; ks < 4; ks++) {
            unsigned a[4][4], b[2][4];
#pragma unroll
            for (int mi = 0; mi < 4; mi++)
                ldsm4(a[mi], aBase + soff + mi * (16 * LDSB) + ks * 32);
#pragma unroll
            for (int nj = 0; nj < 2; nj++)
                ldsm4(b[nj], bBase + soff + nj * (16 * LDSB) + ks * 32);
#pragma unroll
            for (int mi = 0; mi < 4; mi++) {
#pragma unroll
                for (int nb = 0; nb < 2; nb++) {
                    mma16816(acc[mi][2*nb],   a[mi], b[nb][0], b[nb][2]);
                    mma16816(acc[mi][2*nb+1], a[mi], b[nb][1], b[nb][3]);
                }
            }
        }
    }

    const int r0 = trow0 + wm * 64 + (lane >> 2);
    const int cc = ncol0 + wn * 32 + (lane & 3) * 2;
#pragma unroll
    for (int mi = 0; mi < 4; mi++) {
#pragma unroll
        for (int ni = 0; ni < 4; ni++) {
            float* p0 = out + (size_t)(r0 + mi * 16) * H_DIM + cc + ni * 8;
            float* p1 = p0 + 8 * H_DIM;
            *(float2*)p0 = make_float2(acc[mi][ni][0], acc[mi][ni][1]);
            *(float2*)p1 = make_float2(acc[mi][ni][2], acc[mi][ni][3]);
        }
    }
}

// ---------------- tiny setup kernels ----------------
__global__ void zero_kernel() {
    int i = blockIdx.x * 1024 + threadIdx.x;
    if (i < H_DIM) g_counts[i] = 0;
    if (i < 64)    g_paircnt[i] = 0;
}
__global__ void hist_kernel(const int* __restrict__ mask) {
    int s = blockIdx.x * blockDim.x + threadIdx.x;
    if (s < NS_NUM) atomicAdd(&g_counts[mask[s] >> H_SHIFT], 1);
}
__global__ void scan_kernel() {
    __shared__ int chunk[256];
    int tid = threadIdx.x;
    int base = tid * 8;
    int local[8]; int s = 0;
#pragma unroll
    for (int c = 0; c < 8; c++) { local[c] = g_counts[base + c]; s += local[c]; }
    chunk[tid] = s;
    __syncthreads();
    if (tid == 0) {
        int run = 0;
        for (int i = 0; i < 256; i++) { int t = chunk[i]; chunk[i] = run; run += t; }
        g_rowptr[H_DIM] = run;
    }
    __syncthreads();
    int run = chunk[tid];
#pragma unroll
    for (int c = 0; c < 8; c++) {
        g_rowptr[base + c]  = run;
        g_offsets[base + c] = run;
        run += local[c];
    }
}
// scatter: store packed mask (row<<11|col) in CSR order + permuted weights
__global__ void scatter_kernel(const int* __restrict__ mask) {
    int s = blockIdx.x * blockDim.x + threadIdx.x;
    if (s >= NS_NUM) return;
    int m = mask[s];
    int r = m >> H_SHIFT;
    int pos = atomicAdd(&g_offsets[r], 1);
    g_msrt[pos] = m;
#pragma unroll
    for (int e = 0; e < E_NUM; e++)
        g_wsrt[e * NS_NUM + pos] = g_weighted[e * NS_NUM + s];
}

// pair grouping: padded (to 4) exclusive scan over the 64 (e0,e1) pair counts
__global__ void pair_scan_kernel() {
    __shared__ int ptr[65];
    int tid = threadIdx.x;
    if (tid == 0) {
        int run = 0;
        for (int k = 0; k < 64; k++) {
            ptr[k] = run;
            run += ((g_paircnt[k] + 3) >> 2) << 2;
        }
        ptr[64] = run;
        g_total_blocks = run >> 2;
    }
    __syncthreads();
    for (int i = tid; i < 64; i += 256) g_pairoff[i] = ptr[i];
    for (int i = tid; i < PADMAX; i += 256) g_tokord[i] = -1;
    for (int k = tid; k < 64; k += 256) {
        int b0 = ptr[k] >> 2, b1 = ptr[k + 1] >> 2;
        for (int b = b0; b < b1; b++) g_blkpair[b] = k;
    }
}
__global__ void pair_scatter_kernel() {
    int t = blockIdx.x * blockDim.x + threadIdx.x;
    if (t >= T_TOK) return;
    int key = g_e0[t] * 8 + g_e1[t];
    int pos = atomicAdd(&g_pairoff[key], 1);
    g_tokord[pos] = t;
}

// ---------------- weighted: single pass over atoms, all 8 experts ----------------
__global__ __launch_bounds__(256) void weighted_kernel(
    const float* __restrict__ eaw, const float* __restrict__ atoms,
    const float* __restrict__ importance)
{
    __shared__ float wsm[E_NUM][A_NUM];
    int tid = threadIdx.x;
    int w = tid >> 5, lane = tid & 31;
    {
        float v0 = eaw[w * A_NUM + lane];
        float v1 = eaw[w * A_NUM + 32 + lane];
        float mx = fmaxf(v0, v1);
#pragma unroll
        for (int o = 16; o; o >>= 1) mx = fmaxf(mx, __shfl_xor_sync(0xffffffffu, mx, o));
        float e0 = expf(v0 - mx), e1 = expf(v1 - mx);
        float sm = e0 + e1;
#pragma unroll
        for (int o = 16; o; o >>= 1) sm += __shfl_xor_sync(0xffffffffu, sm, o);
        float inv = 1.f / sm;
        wsm[w][lane]      = e0 * inv;
        wsm[w][lane + 32] = e1 * inv;
    }
    __syncthreads();

    int s = blockIdx.x * 256 + tid;
    float acc[E_NUM];
#pragma unroll
    for (int e = 0; e < E_NUM; e++) acc[e] = 0.f;
#pragma unroll 4
    for (int a = 0; a < A_NUM; a++) {
        float va = atoms[a * NS_NUM + s];
#pragma unroll
        for (int e = 0; e < E_NUM; e++) acc[e] += wsm[e][a] * va;
    }
#pragma unroll
    for (int e = 0; e < E_NUM; e++) {
        float imp = importance[e * NS_NUM + s];
        g_weighted[e * NS_NUM + s] = acc[e] * (1.f / (1.f + expf(-imp)));
    }
}

// ---------------- gating: smem-free, warp-per-token ----------------
__global__ __launch_bounds__(256) void gate_kernel(
    const float* __restrict__ x, const float* __restrict__ gw)
{
    int t = blockIdx.x * 8 + (threadIdx.x >> 5);
    int lane = threadIdx.x & 31;
    const float4* xp = (const float4*)(x + (size_t)t * H_DIM);
    const float4* gp = (const float4*)gw;

    float acc[E_NUM];
#pragma unroll
    for (int e = 0; e < E_NUM; e++) acc[e] = 0.f;
#pragma unroll 4
    for (int i = 0; i < 16; i++) {
        float4 v = xp[lane + i * 32];
#pragma unroll
        for (int e = 0; e < E_NUM; e++) {
            float4 g = __ldg(&gp[e * 512 + lane + i * 32]);
            acc[e] += v.x * g.x + v.y * g.y + v.z * g.z + v.w * g.w;
        }
    }
#pragma unroll
    for (int e = 0; e < E_NUM; e++)
#pragma unroll
        for (int o = 16; o; o >>= 1)
            acc[e] += __shfl_xor_sync(0xffffffffu, acc[e], o);

    if (lane == 0) {
        float v[E_NUM];
#pragma unroll
        for (int e = 0; e < E_NUM; e++) v[e] = fminf(50.f, fmaxf(-50.f, acc[e]));
        int i0 = 0;
#pragma unroll
        for (int e = 1; e < E_NUM; e++) if (v[e] > v[i0]) i0 = e;
        int i1 = (i0 == 0) ? 1 : 0;
#pragma unroll
        for (int e = 0; e < E_NUM; e++) if (e != i0 && v[e] > v[i1]) i1 = e;
        float d = expf(v[i1] - v[i0]);
        float inv = 1.f / (1.f + d);
        g_e0[t] = i0; g_e1[t] = i1;
        g_rw0[t] = inv; g_rw1[t] = d * inv;
        atomicAdd(&g_paircnt[i0 * 8 + i1], 1);
    }
}

// ---------------- sparse contrib v5: entry-centric, coalesced LDG, smem-atomic acc ----------------
#define PLANE    2056
#define SP5_SMEM ((4 * PLANE + 4 * H_DIM) * 4 + 64)    // ~65.8KB -> 3 blocks/SM

__global__ __launch_bounds__(256, 3) void sparse5_kernel(
    const float* __restrict__ x, float* __restrict__ out)
{
    extern __shared__ char sm5[];
    float* xs  = (float*)sm5;                 // 4 planes of PLANE floats
    float* acc = xs + 4 * PLANE;              // 4 x H_DIM accumulators
    float* r0s = acc + 4 * H_DIM;
    int*   tks = (int*)(r0s + 4);

    int b = blockIdx.x;
    if (b >= g_total_blocks) return;
    int pair = g_blkpair[b];
    const float4* w0 = (const float4*)(g_wsrt + (pair >> 3) * NS_NUM);
    const float4* w1 = (const float4*)(g_wsrt + (pair & 7) * NS_NUM);
    const int4*   ms = (const int4*)g_msrt;
    int tid = threadIdx.x;

    if (tid < 4) {
        int tok = g_tokord[b * 4 + tid];
        tks[tid] = tok;
        r0s[tid] = tok >= 0 ? g_rw0[tok] : 0.f;
    }
    for (int i = tid; i < 4 * H_DIM; i += 256) acc[i] = 0.f;
    __syncthreads();

    int tk[4]; float r0v[4];
#pragma unroll
    for (int t = 0; t < 4; t++) { tk[t] = tks[t]; r0v[t] = r0s[t]; }

    // stage x rows into planes (coalesced, conflict-free)
#pragma unroll 1
    for (int t = 0; t < 4; t++) {
        float* pl = xs + t * PLANE;
        if (tk[t] >= 0) {
            const float* xp = x + (size_t)tk[t] * H_DIM;
            for (int i = tid; i < H_DIM; i += 256) pl[i] = xp[i];
        } else {
            for (int i = tid; i < H_DIM; i += 256) pl[i] = 0.f;
        }
    }
    __syncthreads();

    // entry-centric main loop: dense vectorized LDG + smem atomics
#pragma unroll 1
    for (int e4 = tid; e4 < NS_NUM / 4; e4 += 256) {
        int4   mm = __ldg(ms + e4);
        float4 a0 = __ldg(w0 + e4);
        float4 a1 = __ldg(w1 + e4);
        int mj[4] = {mm.x, mm.y, mm.z, mm.w};
        float w0j[4] = {a0.x, a0.y, a0.z, a0.w};
        float w1j[4] = {a1.x, a1.y, a1.z, a1.w};
#pragma unroll
        for (int j = 0; j < 4; j++) {
            int r = mj[j] >> H_SHIFT;
            int c = mj[j] & H_MASK;
            float dd = w0j[j] - w1j[j];
#pragma unroll
            for (int t = 0; t < 4; t++) {
                float comb = fmaf(r0v[t], dd, w1j[j]);     // r0*w0 + (1-r0)*w1
                atomicAdd(&acc[t * H_DIM + r], xs[t * PLANE + c] * comb);
            }
        }
    }
    __syncthreads();

    // write out (GEMM result already there; ordered via gemm_done event)
#pragma unroll 1
    for (int t = 0; t < 4; t++) {
        if (tk[t] < 0) continue;
        float* op = out + (size_t)tk[t] * H_DIM;
        const float* ap = acc + t * H_DIM;
        for (int i = tid; i < H_DIM; i += 256) op[i] += ap[i];
    }
}

// ---------------- launch ----------------
extern "C" void kernel_launch(void* const* d_in, const int* in_sizes, int n_in,
                              void* d_out, int out_size)
{
    const float* x     = (const float*)d_in[0];
    const float* gw    = (const float*)d_in[1];
    const float* W     = (const float*)d_in[2];
    const float* atoms = (const float*)d_in[3];
    const float* eaw   = (const float*)d_in[4];
    const float* imp   = (const float*)d_in[5];
    const int*   mask  = (const int*)d_in[6];
    float* out = (float*)d_out;

    (void)in_sizes; (void)n_in; (void)out_size;

    void *xh_p = nullptr, *wh_p = nullptr;
    cudaGetSymbolAddress(&xh_p, g_xh);
    cudaGetSymbolAddress(&wh_p, g_wh);

    cudaFuncSetAttribute(mma_gemm_kernel,
                         cudaFuncAttributeMaxDynamicSharedMemorySize, SMEM_MMA);
    cudaFuncSetAttribute(sparse5_kernel,
                         cudaFuncAttributeMaxDynamicSharedMemorySize, SP5_SMEM);

    cudaStream_t sd = g_fork_res.side;

    cudaEventRecord(g_fork_res.fork, 0);
    cudaStreamWaitEvent(sd, g_fork_res.fork, 0);

    // launches 1,2: fp16 converts (main)
    convert_fp16_kernel<<<(T_TOK * H_DIM / 2) / 256, 256>>>(x, (__half*)xh_p);
    convert_fp16_kernel<<<(H_DIM * H_DIM / 2) / 256, 256>>>(W, (__half*)wh_p);
    // launch 3: zero (side)
    zero_kernel<<<2, 1024, 0, sd>>>();
    // launch 4: GEMM (main) — profiled slot
    mma_gemm_kernel<<<dim3(H_DIM / BN, T_TOK / BM), 512, SMEM_MMA>>>(
        (const __half*)xh_p, (const __half*)wh_p, out);
    cudaEventRecord(g_fork_res.gemm_done, 0);

    // side branch: sparse prep overlaps GEMM; sparse5 waits for GEMM then adds into out
    hist_kernel<<<NS_NUM / 1024, 1024, 0, sd>>>(mask);
    weighted_kernel<<<NS_NUM / 256, 256, 0, sd>>>(eaw, atoms, imp);
    gate_kernel<<<T_TOK / 8, 256, 0, sd>>>(x, gw);
    scan_kernel<<<1, 256, 0, sd>>>();
    pair_scan_kernel<<<1, 256, 0, sd>>>();
    pair_scatter_kernel<<<T_TOK / 256, 256, 0, sd>>>();
    scatter_kernel<<<NS_NUM / 1024, 1024, 0, sd>>>(mask);
    cudaStreamWaitEvent(sd, g_fork_res.gemm_done, 0);
    sparse5_kernel<<<MAXBLK, 256, SP5_SMEM, sd>>>(x, out);
    cudaEventRecord(g_fork_res.join, sd);

    // join side branch back into the capture-origin stream
    cudaStreamWaitEvent(0, g_fork_res.join, 0);
}

// round 12
// speedup vs baseline: 1.2443x; 1.2443x over previous
#include <cuda_runtime.h>
#include <cuda_fp16.h>
#include <math.h>

// Problem constants (fixed shapes: B=2,S=2048,H=2048,E=8,A=64,NS=16384)
#define T_TOK   4096
#define H_DIM   2048
#define E_NUM   8
#define A_NUM   64
#define NS_NUM  16384
#define H_SHIFT 11
#define H_MASK  2047
#define PADMAX  4608
#define MAXBLK  576

// GEMM: C[T,H] = fp16(x) @ fp16(W)^T, K = 2048, fp32 accumulate
#define KC      2048
#define BM      128
#define BN      256
#define BK      64
#define NCH     (KC / BK)            // 32
#define LDSB    144                  // smem row stride bytes (64 fp16 + 16 pad)
#define ABYTES  (BM * LDSB)          // 18432
#define STAGEB  ((BM + BN) * LDSB)   // 55296
#define NSTG    4
#define SMEM_MMA (NSTG * STAGEB)     // 221184

// ---------------- device scratch (no allocations allowed) ----------------
__device__ __half         g_xh[(size_t)T_TOK * KC];     // 16MB fp16(x)
__device__ __half         g_wh[(size_t)H_DIM * KC];     // 8MB  fp16(W)
__device__ float          g_contrib[(size_t)T_TOK * H_DIM];  // 32MB sparse contrib
__device__ float          g_weighted[E_NUM * NS_NUM];
__device__ float          g_wsrt[E_NUM * NS_NUM];       // weighted, CSR entry order
__device__ unsigned short g_colsrt[NS_NUM];             // col per CSR entry
__device__ int            g_counts[H_DIM];
__device__ int            g_rowptr[H_DIM + 1];
__device__ int            g_offsets[H_DIM];
__device__ int            g_e0[T_TOK];
__device__ int            g_e1[T_TOK];
__device__ float          g_rw0[T_TOK];
__device__ float          g_rw1[T_TOK];
// pair grouping (8 tokens per block)
__device__ int            g_paircnt[64];
__device__ int            g_pairoff[64];
__device__ int            g_tokord[PADMAX];
__device__ int            g_blkpair[MAXBLK];
__device__ int            g_total_blocks;

// ---------------- static stream/event resources (created pre-checkpoint) ----------------
struct GraphForkResources {
    cudaStream_t side;
    cudaEvent_t  fork, join;
    GraphForkResources() {
        cudaStreamCreateWithFlags(&side, cudaStreamNonBlocking);
        cudaEventCreateWithFlags(&fork, cudaEventDisableTiming);
        cudaEventCreateWithFlags(&join, cudaEventDisableTiming);
    }
};
static GraphForkResources g_fork_res;

// ---------------- ptx helpers (compute_80-level, safe on compute_103) ----------------
__device__ __forceinline__ unsigned smem_u32(const void* p) {
    unsigned r;
    asm("{ .reg .u64 t; cvta.to.shared.u64 t, %1; cvt.u32.u64 %0, t; }" : "=r"(r) : "l"(p));
    return r;
}
__device__ __forceinline__ void cp16(unsigned dst, const void* src) {
    asm volatile("cp.async.cg.shared.global [%0], [%1], 16;\n" :: "r"(dst), "l"(src));
}
__device__ __forceinline__ void cp_commit() { asm volatile("cp.async.commit_group;\n" ::: "memory"); }
__device__ __forceinline__ void cp_wait2()  { asm volatile("cp.async.wait_group 2;\n" ::: "memory"); }
__device__ __forceinline__ void ldsm4(unsigned* r, unsigned addr) {
    asm volatile("ldmatrix.sync.aligned.m8n8.x4.shared.b16 {%0,%1,%2,%3}, [%4];"
                 : "=r"(r[0]), "=r"(r[1]), "=r"(r[2]), "=r"(r[3]) : "r"(addr));
}
__device__ __forceinline__ void mma16816(float* d, const unsigned* a, unsigned b0, unsigned b1) {
    asm volatile(
        "mma.sync.aligned.m16n8k16.row.col.f32.f16.f16.f32 "
        "{%0,%1,%2,%3}, {%4,%5,%6,%7}, {%8,%9}, {%0,%1,%2,%3};"
        : "+f"(d[0]), "+f"(d[1]), "+f"(d[2]), "+f"(d[3])
        : "r"(a[0]), "r"(a[1]), "r"(a[2]), "r"(a[3]), "r"(b0), "r"(b1));
}

// ---------------- fp16 conversion (x and W share row length 2048) ----------------
__global__ __launch_bounds__(256) void convert_fp16_kernel(
    const float* __restrict__ src, __half* __restrict__ dst)
{
    int idx2 = blockIdx.x * 256 + threadIdx.x;          // float2 index
    float2 v = *(const float2*)(src + (size_t)idx2 * 2);
    __half2 h; h.x = __float2half_rn(v.x); h.y = __float2half_rn(v.y);
    *(__half2*)(dst + (size_t)idx2 * 2) = h;
}

// ---------------- HMMA GEMM: out = Xh @ Wh^T ----------------
// 512 threads, 16 warps as 2(m) x 8(n); warp tile 64x32; 4-stage cp.async pipeline.
__global__ __launch_bounds__(512, 1) void mma_gemm_kernel(
    const __half* __restrict__ A,
    const __half* __restrict__ B,
    float* __restrict__ out)
{
    extern __shared__ __align__(128) char sm[];
    const unsigned smb = smem_u32(sm);
    const int tid  = threadIdx.x;
    const int wid  = tid >> 5, lane = tid & 31;
    const int wm   = wid & 1;          // 0..1 (m)
    const int wn   = wid >> 1;         // 0..7 (n)
    const int trow0 = blockIdx.y * BM;
    const int ncol0 = blockIdx.x * BN;

    const int slot = tid & 7;
    const int rr0  = tid >> 3;         // 0..63
    const __half* aP = A + (size_t)(trow0 + rr0) * KC + slot * 8;
    const __half* bP = B + (size_t)(ncol0 + rr0) * KC + slot * 8;
    const unsigned dBase = rr0 * LDSB + slot * 16;

    const unsigned lrow = lane & 15, lhalf = lane >> 4;
    const unsigned aBase = smb + (wm * 64 + lrow) * LDSB + lhalf * 16;
    const unsigned bBase = smb + ABYTES + (wn * 32 + lrow) * LDSB + lhalf * 16;

    float acc[4][4][4];
#pragma unroll
    for (int i = 0; i < 4; i++)
#pragma unroll
        for (int j = 0; j < 4; j++)
#pragma unroll
            for (int r = 0; r < 4; r++) acc[i][j][r] = 0.f;

#pragma unroll
    for (int c = 0; c < 3; c++) {
        unsigned d = smb + c * STAGEB + dBase;
        const __half* ap = aP + c * BK;
        const __half* bp = bP + c * BK;
#pragma unroll
        for (int i = 0; i < 2; i++) { cp16(d, ap); ap += 64 * KC; d += 64 * LDSB; }
#pragma unroll
        for (int i = 0; i < 4; i++) { cp16(d, bp); bp += 64 * KC; d += 64 * LDSB; }
        cp_commit();
    }

    for (int c = 0; c < NCH; c++) {
        cp_wait2();
        __syncthreads();

        int m = c + 3;
        if (m < NCH) {
            unsigned d = smb + (m & 3) * STAGEB + dBase;
            const __half* ap = aP + m * BK;
            const __half* bp = bP + m * BK;
#pragma unroll
            for (int i = 0; i < 2; i++) { cp16(d, ap); ap += 64 * KC; d += 64 * LDSB; }
#pragma unroll
            for (int i = 0; i < 4; i++) { cp16(d, bp); bp += 64 * KC; d += 64 * LDSB; }
        }
        cp_commit();

        unsigned soff = (unsigned)(c & 3) * STAGEB;
#pragma unroll
        for (int ks = 0; ks < 4; ks++) {
            unsigned a[4][4], b[2][4];
#pragma unroll
            for (int mi = 0; mi < 4; mi++)
                ldsm4(a[mi], aBase + soff + mi * (16 * LDSB) + ks * 32);
#pragma unroll
            for (int nj = 0; nj < 2; nj++)
                ldsm4(b[nj], bBase + soff + nj * (16 * LDSB) + ks * 32);
#pragma unroll
            for (int mi = 0; mi < 4; mi++) {
#pragma unroll
                for (int nb = 0; nb < 2; nb++) {
                    mma16816(acc[mi][2*nb],   a[mi], b[nb][0], b[nb][2]);
                    mma16816(acc[mi][2*nb+1], a[mi], b[nb][1], b[nb][3]);
                }
            }
        }
    }

    const int r0 = trow0 + wm * 64 + (lane >> 2);
    const int cc = ncol0 + wn * 32 + (lane & 3) * 2;
#pragma unroll
    for (int mi = 0; mi < 4; mi++) {
#pragma unroll
        for (int ni = 0; ni < 4; ni++) {
            float* p0 = out + (size_t)(r0 + mi * 16) * H_DIM + cc + ni * 8;
            float* p1 = p0 + 8 * H_DIM;
            *(float2*)p0 = make_float2(acc[mi][ni][0], acc[mi][ni][1]);
            *(float2*)p1 = make_float2(acc[mi][ni][2], acc[mi][ni][3]);
        }
    }
}

// ---------------- final add: out += contrib ----------------
__global__ __launch_bounds__(256) void add_kernel(float* __restrict__ out) {
    size_t i = (size_t)blockIdx.x * 256 + threadIdx.x;
    float4* o = (float4*)out;
    const float4* c = (const float4*)g_contrib;
    float4 a = o[i], b = c[i];
    a.x += b.x; a.y += b.y; a.z += b.z; a.w += b.w;
    o[i] = a;
}

// ---------------- tiny setup kernels ----------------
__global__ void zero_kernel() {
    int i = blockIdx.x * 1024 + threadIdx.x;
    if (i < H_DIM) g_counts[i] = 0;
    if (i < 64)    g_paircnt[i] = 0;
}
__global__ void hist_kernel(const int* __restrict__ mask) {
    int s = blockIdx.x * blockDim.x + threadIdx.x;
    if (s < NS_NUM) atomicAdd(&g_counts[mask[s] >> H_SHIFT], 1);
}
__global__ void scan_kernel() {
    __shared__ int chunk[256];
    int tid = threadIdx.x;
    int base = tid * 8;
    int local[8]; int s = 0;
#pragma unroll
    for (int c = 0; c < 8; c++) { local[c] = g_counts[base + c]; s += local[c]; }
    chunk[tid] = s;
    __syncthreads();
    if (tid == 0) {
        int run = 0;
        for (int i = 0; i < 256; i++) { int t = chunk[i]; chunk[i] = run; run += t; }
        g_rowptr[H_DIM] = run;
    }
    __syncthreads();
    int run = chunk[tid];
#pragma unroll
    for (int c = 0; c < 8; c++) {
        g_rowptr[base + c]  = run;
        g_offsets[base + c] = run;
        run += local[c];
    }
}
__global__ void scatter_kernel(const int* __restrict__ mask) {
    int s = blockIdx.x * blockDim.x + threadIdx.x;
    if (s >= NS_NUM) return;
    int m = mask[s];
    int r = m >> H_SHIFT;
    int c = m & H_MASK;
    int pos = atomicAdd(&g_offsets[r], 1);
    g_colsrt[pos] = (unsigned short)c;
#pragma unroll
    for (int e = 0; e < E_NUM; e++)
        g_wsrt[e * NS_NUM + pos] = g_weighted[e * NS_NUM + s];
}

// pair grouping: padded (to 8) exclusive scan over the 64 (e0,e1) pair counts
__global__ void pair_scan_kernel() {
    __shared__ int ptr[65];
    int tid = threadIdx.x;
    if (tid == 0) {
        int run = 0;
        for (int k = 0; k < 64; k++) {
            ptr[k] = run;
            run += ((g_paircnt[k] + 7) >> 3) << 3;
        }
        ptr[64] = run;
        g_total_blocks = run >> 3;
    }
    __syncthreads();
    for (int i = tid; i < 64; i += 256) g_pairoff[i] = ptr[i];
    for (int i = tid; i < PADMAX; i += 256) g_tokord[i] = -1;
    for (int k = tid; k < 64; k += 256) {
        int b0 = ptr[k] >> 3, b1 = ptr[k + 1] >> 3;
        for (int b = b0; b < b1; b++) g_blkpair[b] = k;
    }
}
__global__ void pair_scatter_kernel() {
    int t = blockIdx.x * blockDim.x + threadIdx.x;
    if (t >= T_TOK) return;
    int key = g_e0[t] * 8 + g_e1[t];
    int pos = atomicAdd(&g_pairoff[key], 1);
    g_tokord[pos] = t;
}

// ---------------- weighted: single pass over atoms, all 8 experts ----------------
__global__ __launch_bounds__(256) void weighted_kernel(
    const float* __restrict__ eaw, const float* __restrict__ atoms,
    const float* __restrict__ importance)
{
    __shared__ float wsm[E_NUM][A_NUM];
    int tid = threadIdx.x;
    int w = tid >> 5, lane = tid & 31;
    {
        float v0 = eaw[w * A_NUM + lane];
        float v1 = eaw[w * A_NUM + 32 + lane];
        float mx = fmaxf(v0, v1);
#pragma unroll
        for (int o = 16; o; o >>= 1) mx = fmaxf(mx, __shfl_xor_sync(0xffffffffu, mx, o));
        float e0 = expf(v0 - mx), e1 = expf(v1 - mx);
        float sm = e0 + e1;
#pragma unroll
        for (int o = 16; o; o >>= 1) sm += __shfl_xor_sync(0xffffffffu, sm, o);
        float inv = 1.f / sm;
        wsm[w][lane]      = e0 * inv;
        wsm[w][lane + 32] = e1 * inv;
    }
    __syncthreads();

    int s = blockIdx.x * 256 + tid;
    float acc[E_NUM];
#pragma unroll
    for (int e = 0; e < E_NUM; e++) acc[e] = 0.f;
#pragma unroll 4
    for (int a = 0; a < A_NUM; a++) {
        float va = atoms[a * NS_NUM + s];
#pragma unroll
        for (int e = 0; e < E_NUM; e++) acc[e] += wsm[e][a] * va;
    }
#pragma unroll
    for (int e = 0; e < E_NUM; e++) {
        float imp = importance[e * NS_NUM + s];
        g_weighted[e * NS_NUM + s] = acc[e] * (1.f / (1.f + expf(-imp)));
    }
}

// ---------------- gating: smem-free, warp-per-token ----------------
__global__ __launch_bounds__(256) void gate_kernel(
    const float* __restrict__ x, const float* __restrict__ gw)
{
    int t = blockIdx.x * 8 + (threadIdx.x >> 5);
    int lane = threadIdx.x & 31;
    const float4* xp = (const float4*)(x + (size_t)t * H_DIM);
    const float4* gp = (const float4*)gw;

    float acc[E_NUM];
#pragma unroll
    for (int e = 0; e < E_NUM; e++) acc[e] = 0.f;
#pragma unroll 4
    for (int i = 0; i < 16; i++) {
        float4 v = xp[lane + i * 32];
#pragma unroll
        for (int e = 0; e < E_NUM; e++) {
            float4 g = __ldg(&gp[e * 512 + lane + i * 32]);
            acc[e] += v.x * g.x + v.y * g.y + v.z * g.z + v.w * g.w;
        }
    }
#pragma unroll
    for (int e = 0; e < E_NUM; e++)
#pragma unroll
        for (int o = 16; o; o >>= 1)
            acc[e] += __shfl_xor_sync(0xffffffffu, acc[e], o);

    if (lane == 0) {
        float v[E_NUM];
#pragma unroll
        for (int e = 0; e < E_NUM; e++) v[e] = fminf(50.f, fmaxf(-50.f, acc[e]));
        int i0 = 0;
#pragma unroll
        for (int e = 1; e < E_NUM; e++) if (v[e] > v[i0]) i0 = e;
        int i1 = (i0 == 0) ? 1 : 0;
#pragma unroll
        for (int e = 0; e < E_NUM; e++) if (e != i0 && v[e] > v[i1]) i1 = e;
        float d = expf(v[i1] - v[i0]);
        float inv = 1.f / (1.f + d);
        g_e0[t] = i0; g_e1[t] = i1;
        g_rw0[t] = inv; g_rw1[t] = d * inv;
        atomicAdd(&g_paircnt[i0 * 8 + i1], 1);
    }
}

// ---------------- sparse contrib v6: 8 tokens/block, 512 threads, transposed x, writes contrib ----------------
// smem: xs2[H_DIM][8] fp32 (64KB) + r0s/tks
#define XSTR     8
#define SP6_SMEM (H_DIM * XSTR * 4 + 128)

__global__ __launch_bounds__(512, 2) void sparse6_kernel(
    const float* __restrict__ x)
{
    extern __shared__ char sm6[];
    float* xs2 = (float*)sm6;                 // [H_DIM][XSTR]
    float* r0s = xs2 + H_DIM * XSTR;
    int*   tks = (int*)(r0s + 8);

    int b = blockIdx.x;
    if (b >= g_total_blocks) return;
    int pair = g_blkpair[b];
    const float* w0 = g_wsrt + (pair >> 3) * NS_NUM;
    const float* w1 = g_wsrt + (pair & 7) * NS_NUM;
    int tid = threadIdx.x;

    if (tid < 8) {
        int tok = g_tokord[b * 8 + tid];
        tks[tid] = tok;
        r0s[tid] = tok >= 0 ? g_rw0[tok] : 0.f;
    }
    __syncthreads();

    float r0v[8];
#pragma unroll
    for (int t = 0; t < 8; t++) r0v[t] = r0s[t];

    // stage x rows transposed: xs2[i*8 + t]
#pragma unroll 1
    for (int t = 0; t < 8; t++) {
        int tok = tks[t];
        if (tok >= 0) {
            const float* xp = x + (size_t)tok * H_DIM;
            for (int i = tid; i < H_DIM; i += 512) xs2[i * XSTR + t] = xp[i];
        } else {
            for (int i = tid; i < H_DIM; i += 512) xs2[i * XSTR + t] = 0.f;
        }
    }
    __syncthreads();

    float acc[4][8];
#pragma unroll
    for (int rr = 0; rr < 4; rr++)
#pragma unroll
        for (int t = 0; t < 8; t++) acc[rr][t] = 0.f;

#pragma unroll 1
    for (int rr = 0; rr < 4; rr++) {
        int row = tid + rr * 512;              // adjacent lanes -> adjacent rows
        int p    = g_rowptr[row];
        int pend = g_rowptr[row + 1];
#pragma unroll 2
        for (; p < pend; p++) {
            float w0p = __ldg(w0 + p);
            float w1p = __ldg(w1 + p);
            int cidx = (int)__ldg(g_colsrt + p);
            float dd = w0p - w1p;
            float4 xa = *(float4*)(xs2 + cidx * XSTR);
            float4 xb = *(float4*)(xs2 + cidx * XSTR + 4);
            acc[rr][0] = fmaf(xa.x, fmaf(r0v[0], dd, w1p), acc[rr][0]);
            acc[rr][1] = fmaf(xa.y, fmaf(r0v[1], dd, w1p), acc[rr][1]);
            acc[rr][2] = fmaf(xa.z, fmaf(r0v[2], dd, w1p), acc[rr][2]);
            acc[rr][3] = fmaf(xa.w, fmaf(r0v[3], dd, w1p), acc[rr][3]);
            acc[rr][4] = fmaf(xb.x, fmaf(r0v[4], dd, w1p), acc[rr][4]);
            acc[rr][5] = fmaf(xb.y, fmaf(r0v[5], dd, w1p), acc[rr][5]);
            acc[rr][6] = fmaf(xb.z, fmaf(r0v[6], dd, w1p), acc[rr][6]);
            acc[rr][7] = fmaf(xb.w, fmaf(r0v[7], dd, w1p), acc[rr][7]);
        }
    }

    // write contrib (coalesced per (t, rr))
#pragma unroll 1
    for (int t = 0; t < 8; t++) {
        int tok = tks[t];
        if (tok < 0) continue;
        float* op = g_contrib + (size_t)tok * H_DIM;
#pragma unroll
        for (int rr = 0; rr < 4; rr++) {
            int row = tid + rr * 512;
            op[row] = acc[rr][t];
        }
    }
}

// ---------------- launch ----------------
extern "C" void kernel_launch(void* const* d_in, const int* in_sizes, int n_in,
                              void* d_out, int out_size)
{
    const float* x     = (const float*)d_in[0];
    const float* gw    = (const float*)d_in[1];
    const float* W     = (const float*)d_in[2];
    const float* atoms = (const float*)d_in[3];
    const float* eaw   = (const float*)d_in[4];
    const float* imp   = (const float*)d_in[5];
    const int*   mask  = (const int*)d_in[6];
    float* out = (float*)d_out;

    (void)in_sizes; (void)n_in; (void)out_size;

    void *xh_p = nullptr, *wh_p = nullptr;
    cudaGetSymbolAddress(&xh_p, g_xh);
    cudaGetSymbolAddress(&wh_p, g_wh);

    cudaFuncSetAttribute(mma_gemm_kernel,
                         cudaFuncAttributeMaxDynamicSharedMemorySize, SMEM_MMA);
    cudaFuncSetAttribute(sparse6_kernel,
                         cudaFuncAttributeMaxDynamicSharedMemorySize, SP6_SMEM);

    cudaStream_t sd = g_fork_res.side;

    cudaEventRecord(g_fork_res.fork, 0);
    cudaStreamWaitEvent(sd, g_fork_res.fork, 0);

    // launches 1,2: fp16 converts (main)
    convert_fp16_kernel<<<(T_TOK * H_DIM / 2) / 256, 256>>>(x, (__half*)xh_p);
    convert_fp16_kernel<<<(H_DIM * H_DIM / 2) / 256, 256>>>(W, (__half*)wh_p);
    // launch 3: zero (side)
    zero_kernel<<<2, 1024, 0, sd>>>();
    // launch 4: GEMM (main) — profiled slot
    mma_gemm_kernel<<<dim3(H_DIM / BN, T_TOK / BM), 512, SMEM_MMA>>>(
        (const __half*)xh_p, (const __half*)wh_p, out);

    // side branch: sparse path into g_contrib; sparse6 overlaps the GEMM on free SMs
    hist_kernel<<<NS_NUM / 1024, 1024, 0, sd>>>(mask);
    weighted_kernel<<<NS_NUM / 256, 256, 0, sd>>>(eaw, atoms, imp);
    gate_kernel<<<T_TOK / 8, 256, 0, sd>>>(x, gw);
    scan_kernel<<<1, 256, 0, sd>>>();
    pair_scan_kernel<<<1, 256, 0, sd>>>();
    pair_scatter_kernel<<<T_TOK / 256, 256, 0, sd>>>();
    scatter_kernel<<<NS_NUM / 1024, 1024, 0, sd>>>(mask);
    sparse6_kernel<<<MAXBLK, 512, SP6_SMEM, sd>>>(x);
    cudaEventRecord(g_fork_res.join, sd);

    // join, then out += contrib
    cudaStreamWaitEvent(0, g_fork_res.join, 0);
    add_kernel<<<(T_TOK * H_DIM / 4) / 256, 256>>>(out);
}